// round 13
// baseline (speedup 1.0000x reference)
#include <cuda_runtime.h>
#include <cuda_fp16.h>
#include <cstdint>

// ---------------------------------------------------------------------------
// Problem constants
// ---------------------------------------------------------------------------
constexpr int N_TOK = 16384;   // T*B
constexpr int C     = 512;
constexpr int O     = 512;
constexpr int RD    = 64;
constexpr int NE    = 8;
constexpr int NSL   = NE + 1;          // 8 expert slices + bias slice

// tcgen05 path tiling: BM=256 (2x M=128 atoms), BN=256, BK=64, 3-stage ring
constexpr int BM_TC = 256, BN_TC = 256, BK_TC = 64;
constexpr int NKT_TC = NSL * C / BK_TC;                    // 72
constexpr unsigned NTILES_TC = (N_TOK / BM_TC) * (O / BN_TC);  // 128

// legacy path tiling (portable PTX pass only)
constexpr int BM_LG = 128, BN_LG = 256, BK_LG = 32;
constexpr int NKT_LG = NSL * (C / BK_LG);                  // 144
constexpr unsigned NTILES_LG = (N_TOK / BM_LG) * (O / BN_LG);  // 256

// Scratch (static device globals — no allocation)
__device__ float g_resp[N_TOK * NE];
__device__ float g_psum[N_TOK / 64];                 // 256 per-block denom sums
__device__ __align__(16) __half g_wh[NSL * O * C];   // fp16 weights: experts 0..7, then bias_w
__device__ unsigned g_tile_ctr;

// ---------------------------------------------------------------------------
// Arch-specific gate: tcgen05 only exists in the sm_103a cubin pass.
// ---------------------------------------------------------------------------
#if defined(__CUDA_ARCH_FEAT_SM103_ALL) || defined(__CUDA_ARCH_FEAT_SM100_ALL) || \
    defined(__CUDA_ARCH_SPECIFIC__) || defined(__CUDA_ARCH_FAMILY_SPECIFIC__)
#define USE_TC 1
#endif

// ---------------------------------------------------------------------------
// Common helpers
// ---------------------------------------------------------------------------
__device__ __forceinline__ uint32_t smem_u32(const void* p) {
    uint32_t a;
    asm("{ .reg .u64 t; cvta.to.shared.u64 t, %1; cvt.u32.u64 %0, t; }" : "=r"(a) : "l"(p));
    return a;
}
__device__ __forceinline__ void cpa16(uint32_t dst, const void* src) {
    asm volatile("cp.async.cg.shared.global [%0], [%1], 16;" :: "r"(dst), "l"(src));
}
#define CP_COMMIT() asm volatile("cp.async.commit_group;" ::: "memory")
#define CP_WAIT0()  asm volatile("cp.async.wait_group 0;" ::: "memory")
#define CP_WAIT1()  asm volatile("cp.async.wait_group 1;" ::: "memory")

__device__ __forceinline__ uint32_t pack_h2(float lo, float hi) {
    __half2 h = __floats2half2_rn(lo, hi);
    return *reinterpret_cast<uint32_t*>(&h);
}
__device__ __forceinline__ uint32_t swz(uint32_t off) {   // SW128: Swizzle<3,4,3>
    return off ^ ((off >> 3) & 0x70);
}

// ---- legacy mma.sync helpers ----
__device__ __forceinline__ void mma_f16(float (&c)[4], const uint32_t (&a)[4], const uint32_t (&b)[2]) {
    asm volatile(
        "mma.sync.aligned.m16n8k16.row.col.f32.f16.f16.f32 "
        "{%0,%1,%2,%3}, {%4,%5,%6,%7}, {%8,%9}, {%0,%1,%2,%3};\n"
        : "+f"(c[0]), "+f"(c[1]), "+f"(c[2]), "+f"(c[3])
        : "r"(a[0]), "r"(a[1]), "r"(a[2]), "r"(a[3]), "r"(b[0]), "r"(b[1]));
}
__device__ __forceinline__ void ldsm_x4(uint32_t& r0, uint32_t& r1, uint32_t& r2, uint32_t& r3,
                                        uint32_t addr) {
    asm volatile("ldmatrix.sync.aligned.m8n8.x4.shared.b16 {%0,%1,%2,%3}, [%4];"
        : "=r"(r0), "=r"(r1), "=r"(r2), "=r"(r3) : "r"(addr));
}

// ---- tcgen05 helpers (arch-specific pass only) ----
#ifdef USE_TC
#define FENCE_ASYNC() asm volatile("fence.proxy.async.shared::cta;" ::: "memory")
__device__ __forceinline__ void mbar_init(uint32_t a, uint32_t cnt) {
    asm volatile("mbarrier.init.shared.b64 [%0], %1;" :: "r"(a), "r"(cnt) : "memory");
}
__device__ __forceinline__ void mbar_wait(uint32_t a, uint32_t parity) {
    asm volatile(
        "{\n\t.reg .pred P;\n\t"
        "W_%=:\n\t"
        "mbarrier.try_wait.parity.shared::cta.b64 P, [%0], %1, 0x989680;\n\t"
        "@P bra.uni D_%=;\n\t"
        "bra.uni W_%=;\n\t"
        "D_%=:\n\t}"
        :: "r"(a), "r"(parity) : "memory");
}
__device__ __forceinline__ uint32_t elect1() {
    uint32_t p;
    asm volatile("{ .reg .pred q; elect.sync _|q, 0xFFFFFFFF; selp.b32 %0, 1, 0, q; }" : "=r"(p));
    return p;
}
__device__ __forceinline__ void tcommit(uint32_t bar) {
    asm volatile(
        "tcgen05.commit.cta_group::1.mbarrier::arrive::one.shared::cluster.b64 [%0];"
        :: "r"(bar) : "memory");
}
__device__ __forceinline__ void mma_f16_ss(uint32_t d, uint64_t da, uint64_t db,
                                           uint32_t idesc, uint32_t en) {
    asm volatile(
        "{\n\t.reg .pred p;\n\t"
        "setp.ne.u32 p, %4, 0;\n\t"
        "tcgen05.mma.cta_group::1.kind::f16 [%0], %1, %2, %3, {%5, %5, %5, %5}, p;\n\t"
        "}"
        :: "r"(d), "l"(da), "l"(db), "r"(idesc), "r"(en), "r"(0u) : "memory");
}
#define TM_ALLOC(sm, n)   asm volatile("tcgen05.alloc.cta_group::1.sync.aligned.shared::cta.b32 [%0], %1;" :: "r"(sm), "r"((uint32_t)(n)) : "memory")
#define TM_RELINQ()       asm volatile("tcgen05.relinquish_alloc_permit.cta_group::1.sync.aligned;")
#define TM_DEALLOC(t, n)  asm volatile("tcgen05.dealloc.cta_group::1.sync.aligned.b32 %0, %1;" :: "r"(t), "r"((uint32_t)(n)))
#define TM_FENCE_AFTER()  asm volatile("tcgen05.fence::after_thread_sync;" ::: "memory")
#define TM_WAIT_LD()      asm volatile("tcgen05.wait::ld.sync.aligned;" ::: "memory")
#define TM_LD_X32(r, addr) \
    asm volatile( \
        "tcgen05.ld.sync.aligned.32x32b.x32.b32 " \
        "{%0, %1, %2, %3, %4, %5, %6, %7, " \
        " %8, %9, %10, %11, %12, %13, %14, %15, " \
        " %16, %17, %18, %19, %20, %21, %22, %23, " \
        " %24, %25, %26, %27, %28, %29, %30, %31}, [%32];" \
        : "=r"((r)[0]),  "=r"((r)[1]),  "=r"((r)[2]),  "=r"((r)[3]), \
          "=r"((r)[4]),  "=r"((r)[5]),  "=r"((r)[6]),  "=r"((r)[7]), \
          "=r"((r)[8]),  "=r"((r)[9]),  "=r"((r)[10]), "=r"((r)[11]), \
          "=r"((r)[12]), "=r"((r)[13]), "=r"((r)[14]), "=r"((r)[15]), \
          "=r"((r)[16]), "=r"((r)[17]), "=r"((r)[18]), "=r"((r)[19]), \
          "=r"((r)[20]), "=r"((r)[21]), "=r"((r)[22]), "=r"((r)[23]), \
          "=r"((r)[24]), "=r"((r)[25]), "=r"((r)[26]), "=r"((r)[27]), \
          "=r"((r)[28]), "=r"((r)[29]), "=r"((r)[30]), "=r"((r)[31]) \
        : "r"(addr))

// SMEM desc: SW128, version=1, SBO=64, LBO=1 (K-major 128B rows)
constexpr uint64_t DESC_BASE =
    (uint64_t(2) << 61) | (uint64_t(1) << 46) | (uint64_t(64) << 32) | (uint64_t(1) << 16);
__device__ __forceinline__ uint64_t make_desc(uint32_t addr) {
    return DESC_BASE | ((uint64_t)(addr >> 4) & 0x3FFF);
}
// idesc kind::f16: dtype=F32 (1<<4), atype=btype=F16 (0), N=256 -> 32<<17, M=128 -> 8<<24
constexpr uint32_t IDESC_F16 = (1u << 4) | (32u << 17) | (8u << 24);
#endif  // USE_TC

// ---------------------------------------------------------------------------
// SMEM layout. tcgen05: 3-stage ring of (A 32KB + B 32KB).
// Scalar constexprs only — namespace-scope constexpr ARRAYS are not visible
// in device code (R12 build failure); stage addresses are computed as
// base + stage*32768.
// ---------------------------------------------------------------------------
constexpr uint32_t OFF_RESP = 0;        // 256*8*4 = 8192
constexpr uint32_t OFF_BIAS = 8192;     // 256*4   = 1024
constexpr uint32_t OFF_TM   = 9216;     // 8
constexpr uint32_t OFF_BARS = 9224;     // 24 (3 mbarriers)
constexpr uint32_t TC_A0    = 10240;    // A stages: 10240 + s*32768
constexpr uint32_t TC_B0    = 108544;   // B stages: 108544 + s*32768, ends 206848
constexpr uint32_t STG      = 32768;
// legacy 80B-pitch tiles reuse these regions
constexpr uint32_t LG_A0 = TC_A0, LG_A1 = TC_A0 + STG;
constexpr uint32_t LG_B0 = TC_B0, LG_B1 = TC_B0 + STG;
constexpr uint32_t SMEM_TOTAL = 206848 + 1024;

// ---------------------------------------------------------------------------
// Phase 1 (fused): blocks [0,256) = GMM responsibilities (64 tokens each);
//                  blocks [256,368) = weight fp16 conversion; ctr reset.
// ---------------------------------------------------------------------------
__global__ __launch_bounds__(256) void prelude_kernel(
    const float* __restrict__ x, const float* __restrict__ map_w,
    const float* __restrict__ map_b, const float* __restrict__ cent,
    const float* __restrict__ prior,
    const float* __restrict__ pw, const float* __restrict__ bw)
{
    const int tid = threadIdx.x;

    if (blockIdx.x >= 256) {      // ---- weight conversion ----
        if (blockIdx.x == 256 && tid == 0) g_tile_ctr = 0;
        const int nTot = NSL * O * C / 4;
        const int nPw  = NE  * O * C / 4;
        const int stride = 112 * 256;
        for (int f = (blockIdx.x - 256) * 256 + tid; f < nTot; f += stride) {
            float4 v = (f < nPw) ? ((const float4*)pw)[f] : ((const float4*)bw)[f - nPw];
            uint2 h;
            h.x = pack_h2(v.x, v.y);
            h.y = pack_h2(v.z, v.w);
            ((uint2*)g_wh)[f] = h;
        }
        return;
    }

    // ---- responsibilities ----
    __shared__ float xs[16][68];
    __shared__ float ws[16][68];
    __shared__ float s_k[64][65];
    __shared__ float s_cent[NE][RD];
    __shared__ float s_cc[NE], s_lp[NE], s_mb[RD];
    __shared__ float s_d[64];

    const int t0 = blockIdx.x * 64;

    for (int i = tid; i < NE * RD; i += 256) s_cent[i / RD][i % RD] = cent[i];
    if (tid < NE) {
        float cc = 0.f;
        #pragma unroll
        for (int j = 0; j < RD; ++j) { float c = cent[tid * RD + j]; cc = fmaf(c, c, cc); }
        s_cc[tid] = cc;
        s_lp[tid] = logf(prior[tid]);
    }
    if (tid < RD) s_mb[tid] = map_b[tid];

    const int ty = tid >> 4, tx = tid & 15;
    const int lr = tid >> 2, lq = tid & 3;

    float acc[4][4];
    #pragma unroll
    for (int i = 0; i < 4; ++i)
        #pragma unroll
        for (int j = 0; j < 4; ++j) acc[i][j] = 0.f;

    for (int ct = 0; ct < C / 16; ++ct) {
        const float4 xv = *(const float4*)(x     + (size_t)(t0 + lr) * C + ct * 16 + lq * 4);
        const float4 wv = *(const float4*)(map_w + (size_t)lr        * C + ct * 16 + lq * 4);
        __syncthreads();
        xs[lq * 4 + 0][lr] = xv.x; xs[lq * 4 + 1][lr] = xv.y;
        xs[lq * 4 + 2][lr] = xv.z; xs[lq * 4 + 3][lr] = xv.w;
        ws[lq * 4 + 0][lr] = wv.x; ws[lq * 4 + 1][lr] = wv.y;
        ws[lq * 4 + 2][lr] = wv.z; ws[lq * 4 + 3][lr] = wv.w;
        __syncthreads();
        #pragma unroll
        for (int kk = 0; kk < 16; ++kk) {
            const float4 a = *(const float4*)&xs[kk][ty * 4];
            const float4 b = *(const float4*)&ws[kk][tx * 4];
            const float av[4] = {a.x, a.y, a.z, a.w};
            const float bv[4] = {b.x, b.y, b.z, b.w};
            #pragma unroll
            for (int i = 0; i < 4; ++i)
                #pragma unroll
                for (int j = 0; j < 4; ++j) acc[i][j] = fmaf(av[i], bv[j], acc[i][j]);
        }
    }
    __syncthreads();
    #pragma unroll
    for (int i = 0; i < 4; ++i)
        #pragma unroll
        for (int j = 0; j < 4; ++j)
            s_k[ty * 4 + i][tx * 4 + j] = acc[i][j] + s_mb[tx * 4 + j];
    __syncthreads();

    if (tid < 64) {
        float kk = 0.f, kc[NE];
        #pragma unroll
        for (int e = 0; e < NE; ++e) kc[e] = 0.f;
        #pragma unroll 8
        for (int j = 0; j < RD; ++j) {
            const float kj = s_k[tid][j];
            kk = fmaf(kj, kj, kk);
            #pragma unroll
            for (int e = 0; e < NE; ++e) kc[e] = fmaf(kj, s_cent[e][j], kc[e]);
        }
        const float LOG2PI = 1.8378770664093453f;
        float lr8[NE], m = -1e30f;
        #pragma unroll
        for (int e = 0; e < NE; ++e) {
            lr8[e] = -0.5f * (kk + s_cc[e] - 2.f * kc[e]) - (RD * 0.5f) * LOG2PI + s_lp[e];
            m = fmaxf(m, lr8[e]);
        }
        float s = 0.f;
        #pragma unroll
        for (int e = 0; e < NE; ++e) s += expf(lr8[e] - m);
        const float denom = m + logf(s);
        float4 r0, r1;
        r0.x = expf(lr8[0] - denom); r0.y = expf(lr8[1] - denom);
        r0.z = expf(lr8[2] - denom); r0.w = expf(lr8[3] - denom);
        r1.x = expf(lr8[4] - denom); r1.y = expf(lr8[5] - denom);
        r1.z = expf(lr8[6] - denom); r1.w = expf(lr8[7] - denom);
        const int tok = t0 + tid;
        *(float4*)&g_resp[tok * NE + 0] = r0;
        *(float4*)&g_resp[tok * NE + 4] = r1;
        s_d[tid] = denom;
    }
    __syncthreads();
    if (tid < 8) {
        float a = 0.f;
        #pragma unroll
        for (int j = 0; j < 8; ++j) a += s_d[tid * 8 + j];
        s_d[tid] = a;
    }
    __syncthreads();
    if (tid == 0) {
        float a = 0.f;
        #pragma unroll
        for (int j = 0; j < 8; ++j) a += s_d[j];
        g_psum[blockIdx.x] = a;
    }
}

// ---------------------------------------------------------------------------
// Phase 2: GEMM + fused loss.  y = A_big @ B_big^T + bias_b
//   tcgen05: one 256x256 tile per CTA, 3-stage ring, prefetch distance 2.
// ---------------------------------------------------------------------------
__global__ __launch_bounds__(256, 1) void moe_gemm(
    const float* __restrict__ x, const float* __restrict__ bias_b,
    float* __restrict__ out, int out_size)
{
    extern __shared__ __align__(128) char smem_raw[];
    const uint32_t sb_raw = smem_u32(smem_raw);
    const uint32_t pad = (1024u - (sb_raw & 1023u)) & 1023u;
    char* smem = smem_raw + pad;
    const uint32_t sb = sb_raw + pad;

    const int tid = threadIdx.x;
    const int warp = tid >> 5, lane = tid & 31;

    float* respS = (float*)(smem + OFF_RESP);
    float* biasS = (float*)(smem + OFF_BIAS);
    __shared__ float s_red[256];

#ifdef USE_TC
    // =================== tcgen05 path: 1 tile per CTA, 3-stage ===================
    if (blockIdx.x >= NTILES_TC) {      // ---- loss CTA ----
        s_red[tid] = g_psum[tid];
        __syncthreads();
        for (int w = 128; w > 0; w >>= 1) {
            if (tid < w) s_red[tid] += s_red[tid + w];
            __syncthreads();
        }
        if (tid == 0) {
            const float loss = -0.1f * s_red[0];
            for (long i = (long)N_TOK * O; i < out_size; ++i) out[i] = loss;
        }
        return;
    }

    const int bm = blockIdx.x >> 1, bn = blockIdx.x & 1;

    if (warp == 0) { TM_ALLOC(sb + OFF_TM, 512); TM_RELINQ(); }
    if (tid == 0) {
        mbar_init(sb + OFF_BARS, 1);
        mbar_init(sb + OFF_BARS + 8, 1);
        mbar_init(sb + OFF_BARS + 16, 1);
    }

    // preload resp tile (8KB) + bias_b slice
    ((float4*)respS)[tid]       = ((const float4*)(g_resp + (size_t)bm * BM_TC * NE))[tid];
    ((float4*)respS)[tid + 256] = ((const float4*)(g_resp + (size_t)bm * BM_TC * NE))[tid + 256];
    if (tid < 64) ((float4*)biasS)[tid] = ((const float4*)(bias_b + bn * BN_TC))[tid];

    float4 xv[16];                      // 64 x-floats: row tid of current i0 chunk
    auto ldgX = [&](int i0c) {
        const float4* p = (const float4*)(x + (size_t)(bm * BM_TC + tid) * C + i0c);
        #pragma unroll
        for (int q = 0; q < 16; ++q) xv[q] = p[q];
    };
    auto stsA = [&](int e, uint32_t offA) {
        const float s = (e < NE) ? respS[tid * NE + e] : 1.0f;
        #pragma unroll
        for (int q = 0; q < 8; ++q) {
            uint4 h;
            h.x = pack_h2(xv[q * 2].x * s,     xv[q * 2].y * s);
            h.y = pack_h2(xv[q * 2].z * s,     xv[q * 2].w * s);
            h.z = pack_h2(xv[q * 2 + 1].x * s, xv[q * 2 + 1].y * s);
            h.w = pack_h2(xv[q * 2 + 1].z * s, xv[q * 2 + 1].w * s);
            *(uint4*)(smem + offA + swz(tid * 128 + q * 16)) = h;
        }
    };
    auto issueB = [&](int e, int i0c, uint32_t offB) {
        const __half* base = g_wh + ((size_t)e * O + bn * BN_TC) * C + i0c;
        #pragma unroll
        for (int it = 0; it < 8; ++it) {
            const int f = tid + it * 256;
            const int row = f >> 3, q = f & 7;
            cpa16(sb + offB + swz(row * 128 + q * 16), base + (size_t)row * C + q * 8);
        }
    };

    __syncthreads();                    // TM_ALLOC + mbar_init done
    uint32_t tmem;
    asm volatile("ld.shared.b32 %0, [%1];" : "=r"(tmem) : "r"(sb + OFF_TM));

    // prologue: stages 0 (kt=0) and 1 (kt=1). kt=0: e=0,i0=0; kt=1: e=1,i0=0.
    ldgX(0);
    issueB(0, 0, TC_B0);
    CP_COMMIT();                        // group g0
    __syncthreads();                    // resp visible for stsA
    stsA(0, TC_A0);
    issueB(1, 0, TC_B0 + STG);
    CP_COMMIT();                        // group g1
    stsA(1, TC_A0 + STG);
    FENCE_ASYNC();

    const uint64_t dA0 = make_desc(sb + TC_A0);
    const uint64_t dB0 = make_desc(sb + TC_B0);
    // stage advance in descriptor units: 32768 bytes / 16 = 2048
    constexpr uint64_t DSTG = STG / 16;

    for (int kt = 0; kt < NKT_TC; ++kt) {
        const int s = kt % 3;
        const uint64_t dAs = dA0 + (uint64_t)s * DSTG;
        const uint64_t dBs = dB0 + (uint64_t)s * DSTG;

        CP_WAIT1();                     // groups ≤ kt complete (kt+1 may be in flight)
        __syncthreads();                // A(kt)/B(kt) visible to all, MMA issue ordered

        // ---- MMA(kt) on stage s ----
        if (warp == 0 && elect1()) {
            #pragma unroll
            for (int k = 0; k < 4; ++k) {
                const uint32_t en = (kt | k) ? 1u : 0u;
                mma_f16_ss(tmem,       dAs + k * 2,        dBs + k * 2, IDESC_F16, en);
                mma_f16_ss(tmem + 256, dAs + 1024 + k * 2, dBs + k * 2, IDESC_F16, en);
            }
            tcommit(sb + OFF_BARS + 8 * s);
        }

        // ---- prefetch kt+2 into stage (kt+2)%3 (= (kt-1)%3) ----
        if (kt + 2 < NKT_TC) {
            if (kt >= 1) {              // stage was consumed by MMA(kt-1)
                const int pb = (kt - 1) % 3;
                mbar_wait(sb + OFF_BARS + 8 * pb, ((kt - 1) / 3) & 1);
            }
            const int e2 = (kt + 2) % NSL;
            const int i2 = ((kt + 2) / NSL) * BK_TC;
            const uint32_t s2 = (uint32_t)((kt + 2) % 3) * STG;
            issueB(e2, i2, TC_B0 + s2);
            CP_COMMIT();                // group g_{kt+2}
            if (e2 == 0) ldgX(i2);
            stsA(e2, TC_A0 + s2);
            FENCE_ASYNC();
        } else {
            CP_COMMIT();                // empty group keeps wait_group counting uniform
        }
    }

    // last MMA: kt=71 -> bar[71%3=2], use #23 -> parity 1
    mbar_wait(sb + OFF_BARS + 8 * ((NKT_TC - 1) % 3), ((NKT_TC - 1) / 3) & 1);
    TM_FENCE_AFTER();

    // epilogue: warps 0-3 -> M-atom0, warps 4-7 -> M-atom1
    {
        const int atom = warp >> 2, wsub = warp & 3;
        const int row = bm * BM_TC + atom * 128 + wsub * 32 + lane;
        const uint32_t tbase = tmem + atom * 256;
        float* dst = out + (size_t)row * O + bn * BN_TC;
        #pragma unroll 1
        for (int c = 0; c < 8; ++c) {
            uint32_t r[32];
            TM_LD_X32(r, tbase + c * 32);
            TM_WAIT_LD();
            #pragma unroll
            for (int q = 0; q < 8; ++q) {
                const float4 bb = *(const float4*)&biasS[c * 32 + q * 4];
                float4 v;
                v.x = __uint_as_float(r[q * 4 + 0]) + bb.x;
                v.y = __uint_as_float(r[q * 4 + 1]) + bb.y;
                v.z = __uint_as_float(r[q * 4 + 2]) + bb.z;
                v.w = __uint_as_float(r[q * 4 + 3]) + bb.w;
                *(float4*)(dst + c * 32 + q * 4) = v;
            }
        }
    }
    __syncthreads();
    if (warp == 0) TM_DEALLOC(tmem, 512);

#else
    // =================== legacy mma.sync fallback (R8-proven) ===================
    __shared__ unsigned s_tile;
    const int wm = warp >> 2, wn = warp & 3;
    const int g = lane >> 2, tg = lane & 3;
    const int arow = tid >> 1;
    const int aseg = tid & 1;

    const uint32_t aOff = (uint32_t)(wm * 64 + (lane & 15)) * 80 + (uint32_t)(lane >> 4) * 16;
    const uint32_t bOff = (uint32_t)(wn * 64 + (lane & 7)) * 80 + (uint32_t)(lane >> 3) * 16;

    for (;;) {
        __syncthreads();
        if (tid == 0) s_tile = atomicAdd(&g_tile_ctr, 1u);
        __syncthreads();
        const unsigned t = s_tile;
        if (t > NTILES_LG) break;
        if (t == NTILES_LG) {
            s_red[tid] = g_psum[tid];
            __syncthreads();
            for (int w = 128; w > 0; w >>= 1) {
                if (tid < w) s_red[tid] += s_red[tid + w];
                __syncthreads();
            }
            if (tid == 0) {
                const float loss = -0.1f * s_red[0];
                for (long i = (long)N_TOK * O; i < out_size; ++i) out[i] = loss;
            }
            continue;
        }
        const int bm = t >> 1, bn = t & 1;

        ((float4*)respS)[tid] = ((const float4*)(g_resp + (size_t)bm * BM_LG * NE))[tid];
        if (tid < 64) ((float4*)biasS)[tid] = ((const float4*)(bias_b + bn * BN_LG))[tid];

        float4 xv[4];
        auto ldgX = [&](int i0c) {
            const float4* p = (const float4*)(x + (size_t)(bm * BM_LG + arow) * C + i0c + aseg * 16);
            xv[0] = p[0]; xv[1] = p[1]; xv[2] = p[2]; xv[3] = p[3];
        };
        auto stsA = [&](int e, uint32_t offA) {
            const float s = (e < NE) ? respS[arow * NE + e] : 1.0f;
            uint4 h0, h1;
            h0.x = pack_h2(xv[0].x * s, xv[0].y * s);
            h0.y = pack_h2(xv[0].z * s, xv[0].w * s);
            h0.z = pack_h2(xv[1].x * s, xv[1].y * s);
            h0.w = pack_h2(xv[1].z * s, xv[1].w * s);
            h1.x = pack_h2(xv[2].x * s, xv[2].y * s);
            h1.y = pack_h2(xv[2].z * s, xv[2].w * s);
            h1.z = pack_h2(xv[3].x * s, xv[3].y * s);
            h1.w = pack_h2(xv[3].z * s, xv[3].w * s);
            uint4* dst = (uint4*)(smem + offA + arow * 80 + aseg * 32);
            dst[0] = h0; dst[1] = h1;
        };
        auto issueB = [&](int e, int i0c, uint32_t offB) {
            const __half* base = g_wh + ((size_t)e * O + bn * BN_LG) * C + i0c;
            #pragma unroll
            for (int k = 0; k < 4; ++k) {
                const int c = tid + k * 256;
                const int row = c >> 2, q = c & 3;
                cpa16(sb + offB + row * 80 + q * 16, base + (size_t)row * C + q * 8);
            }
        };

        float acc[4][8][4];
        #pragma unroll
        for (int a = 0; a < 4; ++a)
            #pragma unroll
            for (int b = 0; b < 8; ++b)
                #pragma unroll
                for (int c = 0; c < 4; ++c) acc[a][b][c] = 0.f;

        ldgX(0);
        issueB(0, 0, LG_B0);
        CP_COMMIT();
        __syncthreads();
        stsA(0, LG_A0);
        CP_WAIT0();
        __syncthreads();

        for (int kt = 0; kt < NKT_LG; ++kt) {
            const int s = kt & 1;
            const bool more = (kt + 1 < NKT_LG);
            int e1 = 0;
            if (more) {
                e1 = (kt + 1) % NSL;
                const int i1 = ((kt + 1) / NSL) * BK_LG;
                issueB(e1, i1, s ? LG_B0 : LG_B1);
                CP_COMMIT();
                if (e1 == 0) ldgX(i1);
            }
            {
                const uint32_t A0 = sb + (s ? LG_A1 : LG_A0);
                const uint32_t B0 = sb + (s ? LG_B1 : LG_B0);
                uint32_t af[2][4][4], bf[2][8][2];
                #pragma unroll
                for (int mt = 0; mt < 4; ++mt) {
                    ldsm_x4(af[0][mt][0], af[0][mt][1], af[0][mt][2], af[0][mt][3],
                            A0 + aOff + mt * 1280);
                    ldsm_x4(af[1][mt][0], af[1][mt][1], af[1][mt][2], af[1][mt][3],
                            A0 + aOff + mt * 1280 + 32);
                }
                #pragma unroll
                for (int nt = 0; nt < 8; ++nt) {
                    uint32_t r0, r1, r2, r3;
                    ldsm_x4(r0, r1, r2, r3, B0 + bOff + nt * 640);
                    bf[0][nt][0] = r0; bf[0][nt][1] = r1;
                    bf[1][nt][0] = r2; bf[1][nt][1] = r3;
                }
                #pragma unroll
                for (int ks = 0; ks < 2; ++ks)
                    #pragma unroll
                    for (int mt = 0; mt < 4; ++mt)
                        #pragma unroll
                        for (int nt = 0; nt < 8; ++nt)
                            mma_f16(acc[mt][nt], af[ks][mt], bf[ks][nt]);
            }
            if (more) {
                stsA(e1, s ? LG_A0 : LG_A1);
                CP_WAIT0();
            }
            __syncthreads();
        }

        #pragma unroll
        for (int mt = 0; mt < 4; ++mt) {
            const int row = bm * BM_LG + wm * 64 + mt * 16 + g;
            #pragma unroll
            for (int nt = 0; nt < 8; ++nt) {
                const int cb = wn * 64 + nt * 8 + tg * 2;
                const float b0 = biasS[cb], b1 = biasS[cb + 1];
                float2 v0 = make_float2(acc[mt][nt][0] + b0, acc[mt][nt][1] + b1);
                float2 v1 = make_float2(acc[mt][nt][2] + b0, acc[mt][nt][3] + b1);
                float* dst = out + (size_t)row * O + bn * BN_LG + cb;
                *(float2*)dst = v0;
                *(float2*)(dst + 8 * O) = v1;
            }
        }
    }
#endif
}

// ---------------------------------------------------------------------------
extern "C" void kernel_launch(void* const* d_in, const int* in_sizes, int n_in,
                              void* d_out, int out_size)
{
    const float* x      = (const float*)d_in[0];
    // d_in[1] = key_feat, ignored by the forward pass
    const float* map_w  = (const float*)d_in[2];
    const float* map_b  = (const float*)d_in[3];
    const float* cent   = (const float*)d_in[4];
    const float* prior  = (const float*)d_in[5];
    const float* pw_w   = (const float*)d_in[6];
    const float* bias_w = (const float*)d_in[7];
    const float* bias_b = (const float*)d_in[8];
    float* out = (float*)d_out;

    cudaFuncSetAttribute(moe_gemm, cudaFuncAttributeMaxDynamicSharedMemorySize, SMEM_TOTAL);

    prelude_kernel<<<368, 256>>>(x, map_w, map_b, cent, prior, pw_w, bias_w);
    moe_gemm<<<NTILES_TC + 1, 256, SMEM_TOTAL>>>(x, bias_b, out, out_size);
}

// round 14
// speedup vs baseline: 1.1219x; 1.1219x over previous
#include <cuda_runtime.h>
#include <cuda_fp16.h>
#include <cstdint>

// ---------------------------------------------------------------------------
// Problem constants
// ---------------------------------------------------------------------------
constexpr int N_TOK = 16384;   // T*B
constexpr int C     = 512;
constexpr int O     = 512;
constexpr int RD    = 64;
constexpr int NE    = 8;
constexpr int NSL   = NE + 1;          // 8 expert slices + bias slice

// tcgen05 path tiling: BM=256 (2x M=128 atoms), BN=256, BK=64, 3-stage ring
constexpr int BM_TC = 256, BN_TC = 256, BK_TC = 64;
constexpr int NKT_TC = NSL * C / BK_TC;                    // 72
constexpr unsigned NTILES_TC = (N_TOK / BM_TC) * (O / BN_TC);  // 128
constexpr int FINAL_PH = ((NKT_TC / 3 - 1) & 1);           // 1

// legacy path tiling (portable PTX pass only)
constexpr int BM_LG = 128, BN_LG = 256, BK_LG = 32;
constexpr int NKT_LG = NSL * (C / BK_LG);                  // 144
constexpr unsigned NTILES_LG = (N_TOK / BM_LG) * (O / BN_LG);  // 256

// Scratch (static device globals — no allocation)
__device__ float g_resp[N_TOK * NE];
__device__ float g_psum[N_TOK / 64];                 // 256 per-block denom sums
__device__ __align__(16) __half g_wh[NSL * O * C];   // fp16 weights: experts 0..7, then bias_w
__device__ unsigned g_tile_ctr;

// ---------------------------------------------------------------------------
// Arch-specific gate: tcgen05 only exists in the sm_103a cubin pass.
// ---------------------------------------------------------------------------
#if defined(__CUDA_ARCH_FEAT_SM103_ALL) || defined(__CUDA_ARCH_FEAT_SM100_ALL) || \
    defined(__CUDA_ARCH_SPECIFIC__) || defined(__CUDA_ARCH_FAMILY_SPECIFIC__)
#define USE_TC 1
#endif

// ---------------------------------------------------------------------------
// Common helpers
// ---------------------------------------------------------------------------
__device__ __forceinline__ uint32_t smem_u32(const void* p) {
    uint32_t a;
    asm("{ .reg .u64 t; cvta.to.shared.u64 t, %1; cvt.u32.u64 %0, t; }" : "=r"(a) : "l"(p));
    return a;
}
__device__ __forceinline__ void cpa16(uint32_t dst, const void* src) {
    asm volatile("cp.async.cg.shared.global [%0], [%1], 16;" :: "r"(dst), "l"(src));
}
#define CP_COMMIT() asm volatile("cp.async.commit_group;" ::: "memory")
#define CP_WAIT0()  asm volatile("cp.async.wait_group 0;" ::: "memory")

__device__ __forceinline__ uint32_t pack_h2(float lo, float hi) {
    __half2 h = __floats2half2_rn(lo, hi);
    return *reinterpret_cast<uint32_t*>(&h);
}
__device__ __forceinline__ uint32_t swz(uint32_t off) {   // SW128: Swizzle<3,4,3>
    return off ^ ((off >> 3) & 0x70);
}

// ---- legacy mma.sync helpers ----
__device__ __forceinline__ void mma_f16(float (&c)[4], const uint32_t (&a)[4], const uint32_t (&b)[2]) {
    asm volatile(
        "mma.sync.aligned.m16n8k16.row.col.f32.f16.f16.f32 "
        "{%0,%1,%2,%3}, {%4,%5,%6,%7}, {%8,%9}, {%0,%1,%2,%3};\n"
        : "+f"(c[0]), "+f"(c[1]), "+f"(c[2]), "+f"(c[3])
        : "r"(a[0]), "r"(a[1]), "r"(a[2]), "r"(a[3]), "r"(b[0]), "r"(b[1]));
}
__device__ __forceinline__ void ldsm_x4(uint32_t& r0, uint32_t& r1, uint32_t& r2, uint32_t& r3,
                                        uint32_t addr) {
    asm volatile("ldmatrix.sync.aligned.m8n8.x4.shared.b16 {%0,%1,%2,%3}, [%4];"
        : "=r"(r0), "=r"(r1), "=r"(r2), "=r"(r3) : "r"(addr));
}

// ---- tcgen05 helpers (arch-specific pass only) ----
#ifdef USE_TC
#define FENCE_ASYNC() asm volatile("fence.proxy.async.shared::cta;" ::: "memory")
__device__ __forceinline__ void mbar_init(uint32_t a, uint32_t cnt) {
    asm volatile("mbarrier.init.shared.b64 [%0], %1;" :: "r"(a), "r"(cnt) : "memory");
}
__device__ __forceinline__ void mbar_arrive(uint32_t a) {
    asm volatile("mbarrier.arrive.shared::cta.b64 _, [%0];" :: "r"(a) : "memory");
}
__device__ __forceinline__ void cpa_mbar_arrive(uint32_t a) {
    asm volatile("cp.async.mbarrier.arrive.shared::cta.b64 [%0];" :: "r"(a) : "memory");
}
__device__ __forceinline__ void mbar_wait(uint32_t a, uint32_t parity) {
    asm volatile(
        "{\n\t.reg .pred P;\n\t"
        "W_%=:\n\t"
        "mbarrier.try_wait.parity.shared::cta.b64 P, [%0], %1, 0x989680;\n\t"
        "@P bra.uni D_%=;\n\t"
        "bra.uni W_%=;\n\t"
        "D_%=:\n\t}"
        :: "r"(a), "r"(parity) : "memory");
}
__device__ __forceinline__ uint32_t elect1() {
    uint32_t p;
    asm volatile("{ .reg .pred q; elect.sync _|q, 0xFFFFFFFF; selp.b32 %0, 1, 0, q; }" : "=r"(p));
    return p;
}
__device__ __forceinline__ void tcommit(uint32_t bar) {
    asm volatile(
        "tcgen05.commit.cta_group::1.mbarrier::arrive::one.shared::cluster.b64 [%0];"
        :: "r"(bar) : "memory");
}
__device__ __forceinline__ void mma_f16_ss(uint32_t d, uint64_t da, uint64_t db,
                                           uint32_t idesc, uint32_t en) {
    asm volatile(
        "{\n\t.reg .pred p;\n\t"
        "setp.ne.u32 p, %4, 0;\n\t"
        "tcgen05.mma.cta_group::1.kind::f16 [%0], %1, %2, %3, {%5, %5, %5, %5}, p;\n\t"
        "}"
        :: "r"(d), "l"(da), "l"(db), "r"(idesc), "r"(en), "r"(0u) : "memory");
}
#define TM_ALLOC(sm, n)   asm volatile("tcgen05.alloc.cta_group::1.sync.aligned.shared::cta.b32 [%0], %1;" :: "r"(sm), "r"((uint32_t)(n)) : "memory")
#define TM_RELINQ()       asm volatile("tcgen05.relinquish_alloc_permit.cta_group::1.sync.aligned;")
#define TM_DEALLOC(t, n)  asm volatile("tcgen05.dealloc.cta_group::1.sync.aligned.b32 %0, %1;" :: "r"(t), "r"((uint32_t)(n)))
#define TM_FENCE_AFTER()  asm volatile("tcgen05.fence::after_thread_sync;" ::: "memory")
#define TM_WAIT_LD()      asm volatile("tcgen05.wait::ld.sync.aligned;" ::: "memory")
#define TM_LD_X32(r, addr) \
    asm volatile( \
        "tcgen05.ld.sync.aligned.32x32b.x32.b32 " \
        "{%0, %1, %2, %3, %4, %5, %6, %7, " \
        " %8, %9, %10, %11, %12, %13, %14, %15, " \
        " %16, %17, %18, %19, %20, %21, %22, %23, " \
        " %24, %25, %26, %27, %28, %29, %30, %31}, [%32];" \
        : "=r"((r)[0]),  "=r"((r)[1]),  "=r"((r)[2]),  "=r"((r)[3]), \
          "=r"((r)[4]),  "=r"((r)[5]),  "=r"((r)[6]),  "=r"((r)[7]), \
          "=r"((r)[8]),  "=r"((r)[9]),  "=r"((r)[10]), "=r"((r)[11]), \
          "=r"((r)[12]), "=r"((r)[13]), "=r"((r)[14]), "=r"((r)[15]), \
          "=r"((r)[16]), "=r"((r)[17]), "=r"((r)[18]), "=r"((r)[19]), \
          "=r"((r)[20]), "=r"((r)[21]), "=r"((r)[22]), "=r"((r)[23]), \
          "=r"((r)[24]), "=r"((r)[25]), "=r"((r)[26]), "=r"((r)[27]), \
          "=r"((r)[28]), "=r"((r)[29]), "=r"((r)[30]), "=r"((r)[31]) \
        : "r"(addr))

// SMEM desc: SW128, version=1, SBO=64, LBO=1 (K-major 128B rows)
constexpr uint64_t DESC_BASE =
    (uint64_t(2) << 61) | (uint64_t(1) << 46) | (uint64_t(64) << 32) | (uint64_t(1) << 16);
__device__ __forceinline__ uint64_t make_desc(uint32_t addr) {
    return DESC_BASE | ((uint64_t)(addr >> 4) & 0x3FFF);
}
// idesc kind::f16: dtype=F32 (1<<4), atype=btype=F16 (0), N=256 -> 32<<17, M=128 -> 8<<24
constexpr uint32_t IDESC_F16 = (1u << 4) | (32u << 17) | (8u << 24);
#endif  // USE_TC

// ---------------------------------------------------------------------------
// SMEM layout. tcgen05: 3-stage ring of (A 32KB + B 32KB), scalar bases.
// ---------------------------------------------------------------------------
constexpr uint32_t OFF_RESP  = 0;        // 256*8*4 = 8192
constexpr uint32_t OFF_BIAS  = 8192;     // 256*4   = 1024
constexpr uint32_t OFF_TM    = 9216;     // 8
constexpr uint32_t OFF_FULL  = 9224;     // 3 x 8B
constexpr uint32_t OFF_EMPTY = 9248;     // 3 x 8B
constexpr uint32_t TC_A0     = 10240;    // A stages: +s*32768
constexpr uint32_t TC_B0     = 108544;   // B stages: +s*32768, ends 206848
constexpr uint32_t STG       = 32768;
// legacy 80B-pitch tiles reuse these regions
constexpr uint32_t LG_A0 = TC_A0, LG_A1 = TC_A0 + STG;
constexpr uint32_t LG_B0 = TC_B0, LG_B1 = TC_B0 + STG;
constexpr uint32_t SMEM_TOTAL = 206848 + 1024;

// ---------------------------------------------------------------------------
// Phase 1 (fused): blocks [0,256) = GMM responsibilities (64 tokens each);
//                  blocks [256,368) = weight fp16 conversion; ctr reset.
// ---------------------------------------------------------------------------
__global__ __launch_bounds__(256) void prelude_kernel(
    const float* __restrict__ x, const float* __restrict__ map_w,
    const float* __restrict__ map_b, const float* __restrict__ cent,
    const float* __restrict__ prior,
    const float* __restrict__ pw, const float* __restrict__ bw)
{
    const int tid = threadIdx.x;

    if (blockIdx.x >= 256) {      // ---- weight conversion ----
        if (blockIdx.x == 256 && tid == 0) g_tile_ctr = 0;
        const int nTot = NSL * O * C / 4;
        const int nPw  = NE  * O * C / 4;
        const int stride = 112 * 256;
        for (int f = (blockIdx.x - 256) * 256 + tid; f < nTot; f += stride) {
            float4 v = (f < nPw) ? ((const float4*)pw)[f] : ((const float4*)bw)[f - nPw];
            uint2 h;
            h.x = pack_h2(v.x, v.y);
            h.y = pack_h2(v.z, v.w);
            ((uint2*)g_wh)[f] = h;
        }
        return;
    }

    // ---- responsibilities ----
    __shared__ float xs[16][68];
    __shared__ float ws[16][68];
    __shared__ float s_k[64][65];
    __shared__ float s_cent[NE][RD];
    __shared__ float s_cc[NE], s_lp[NE], s_mb[RD];
    __shared__ float s_d[64];

    const int t0 = blockIdx.x * 64;

    for (int i = tid; i < NE * RD; i += 256) s_cent[i / RD][i % RD] = cent[i];
    if (tid < NE) {
        float cc = 0.f;
        #pragma unroll
        for (int j = 0; j < RD; ++j) { float c = cent[tid * RD + j]; cc = fmaf(c, c, cc); }
        s_cc[tid] = cc;
        s_lp[tid] = logf(prior[tid]);
    }
    if (tid < RD) s_mb[tid] = map_b[tid];

    const int ty = tid >> 4, tx = tid & 15;
    const int lr = tid >> 2, lq = tid & 3;

    float acc[4][4];
    #pragma unroll
    for (int i = 0; i < 4; ++i)
        #pragma unroll
        for (int j = 0; j < 4; ++j) acc[i][j] = 0.f;

    for (int ct = 0; ct < C / 16; ++ct) {
        const float4 xv = *(const float4*)(x     + (size_t)(t0 + lr) * C + ct * 16 + lq * 4);
        const float4 wv = *(const float4*)(map_w + (size_t)lr        * C + ct * 16 + lq * 4);
        __syncthreads();
        xs[lq * 4 + 0][lr] = xv.x; xs[lq * 4 + 1][lr] = xv.y;
        xs[lq * 4 + 2][lr] = xv.z; xs[lq * 4 + 3][lr] = xv.w;
        ws[lq * 4 + 0][lr] = wv.x; ws[lq * 4 + 1][lr] = wv.y;
        ws[lq * 4 + 2][lr] = wv.z; ws[lq * 4 + 3][lr] = wv.w;
        __syncthreads();
        #pragma unroll
        for (int kk = 0; kk < 16; ++kk) {
            const float4 a = *(const float4*)&xs[kk][ty * 4];
            const float4 b = *(const float4*)&ws[kk][tx * 4];
            const float av[4] = {a.x, a.y, a.z, a.w};
            const float bv[4] = {b.x, b.y, b.z, b.w};
            #pragma unroll
            for (int i = 0; i < 4; ++i)
                #pragma unroll
                for (int j = 0; j < 4; ++j) acc[i][j] = fmaf(av[i], bv[j], acc[i][j]);
        }
    }
    __syncthreads();
    #pragma unroll
    for (int i = 0; i < 4; ++i)
        #pragma unroll
        for (int j = 0; j < 4; ++j)
            s_k[ty * 4 + i][tx * 4 + j] = acc[i][j] + s_mb[tx * 4 + j];
    __syncthreads();

    if (tid < 64) {
        float kk = 0.f, kc[NE];
        #pragma unroll
        for (int e = 0; e < NE; ++e) kc[e] = 0.f;
        #pragma unroll 8
        for (int j = 0; j < RD; ++j) {
            const float kj = s_k[tid][j];
            kk = fmaf(kj, kj, kk);
            #pragma unroll
            for (int e = 0; e < NE; ++e) kc[e] = fmaf(kj, s_cent[e][j], kc[e]);
        }
        const float LOG2PI = 1.8378770664093453f;
        float lr8[NE], m = -1e30f;
        #pragma unroll
        for (int e = 0; e < NE; ++e) {
            lr8[e] = -0.5f * (kk + s_cc[e] - 2.f * kc[e]) - (RD * 0.5f) * LOG2PI + s_lp[e];
            m = fmaxf(m, lr8[e]);
        }
        float s = 0.f;
        #pragma unroll
        for (int e = 0; e < NE; ++e) s += expf(lr8[e] - m);
        const float denom = m + logf(s);
        float4 r0, r1;
        r0.x = expf(lr8[0] - denom); r0.y = expf(lr8[1] - denom);
        r0.z = expf(lr8[2] - denom); r0.w = expf(lr8[3] - denom);
        r1.x = expf(lr8[4] - denom); r1.y = expf(lr8[5] - denom);
        r1.z = expf(lr8[6] - denom); r1.w = expf(lr8[7] - denom);
        const int tok = t0 + tid;
        *(float4*)&g_resp[tok * NE + 0] = r0;
        *(float4*)&g_resp[tok * NE + 4] = r1;
        s_d[tid] = denom;
    }
    __syncthreads();
    if (tid < 8) {
        float a = 0.f;
        #pragma unroll
        for (int j = 0; j < 8; ++j) a += s_d[tid * 8 + j];
        s_d[tid] = a;
    }
    __syncthreads();
    if (tid == 0) {
        float a = 0.f;
        #pragma unroll
        for (int j = 0; j < 8; ++j) a += s_d[j];
        g_psum[blockIdx.x] = a;
    }
}

// ---------------------------------------------------------------------------
// Phase 2: GEMM + fused loss.  y = A_big @ B_big^T + bias_b
//   tcgen05: warp-specialized. Warps 0-7 = producers (256 threads, same
//   per-thread A/B mapping as before), warp 8 = MMA issuer. 3-stage ring,
//   full/empty mbarriers, no __syncthreads / wait_group in the main loop.
// ---------------------------------------------------------------------------
__global__ __launch_bounds__(288, 1) void moe_gemm(
    const float* __restrict__ x, const float* __restrict__ bias_b,
    float* __restrict__ out, int out_size)
{
    extern __shared__ __align__(128) char smem_raw[];
    const uint32_t sb_raw = smem_u32(smem_raw);
    const uint32_t pad = (1024u - (sb_raw & 1023u)) & 1023u;
    char* smem = smem_raw + pad;
    const uint32_t sb = sb_raw + pad;

    const int tid = threadIdx.x;
    const int warp = tid >> 5, lane = tid & 31;

    float* respS = (float*)(smem + OFF_RESP);
    float* biasS = (float*)(smem + OFF_BIAS);
    __shared__ float s_red[256];

#ifdef USE_TC
    // =================== tcgen05 warp-specialized path ===================
    if (blockIdx.x >= NTILES_TC) {      // ---- loss CTA ----
        if (tid >= 256) return;
        s_red[tid] = g_psum[tid];
        __syncthreads();
        for (int w = 128; w > 0; w >>= 1) {
            if (tid < w) s_red[tid] += s_red[tid + w];
            __syncthreads();
        }
        if (tid == 0) {
            const float loss = -0.1f * s_red[0];
            for (long i = (long)N_TOK * O; i < out_size; ++i) out[i] = loss;
        }
        return;
    }

    const int bm = blockIdx.x >> 1, bn = blockIdx.x & 1;

    if (warp == 0) { TM_ALLOC(sb + OFF_TM, 512); TM_RELINQ(); }
    if (tid == 0) {
        #pragma unroll
        for (int s = 0; s < 3; ++s) {
            mbar_init(sb + OFF_FULL  + 8 * s, 256);  // 256 explicit arrives/phase
            mbar_init(sb + OFF_EMPTY + 8 * s, 1);    // tcgen05.commit
        }
    }

    // preload resp tile (8KB) + bias_b slice (producers only)
    if (tid < 256) {
        ((float4*)respS)[tid]       = ((const float4*)(g_resp + (size_t)bm * BM_TC * NE))[tid];
        ((float4*)respS)[tid + 256] = ((const float4*)(g_resp + (size_t)bm * BM_TC * NE))[tid + 256];
        if (tid < 64) ((float4*)biasS)[tid] = ((const float4*)(bias_b + bn * BN_TC))[tid];
    }

    __syncthreads();                    // alloc + init + resp/bias visible
    uint32_t tmem;
    asm volatile("ld.shared.b32 %0, [%1];" : "=r"(tmem) : "r"(sb + OFF_TM));

    const uint64_t dA0 = make_desc(sb + TC_A0);
    const uint64_t dB0 = make_desc(sb + TC_B0);
    constexpr uint64_t DSTG = STG / 16;   // stage advance in 16B descriptor units

    if (warp < 8) {
        // ======================= producers =======================
        float4 xv[16];                  // 64 x-floats: row tid, current i0 chunk
        auto ldgX = [&](int i0c) {
            const float4* p = (const float4*)(x + (size_t)(bm * BM_TC + tid) * C + i0c);
            #pragma unroll
            for (int q = 0; q < 16; ++q) xv[q] = p[q];
        };
        auto stsA = [&](int e, uint32_t offA) {
            const float s = (e < NE) ? respS[tid * NE + e] : 1.0f;
            #pragma unroll
            for (int q = 0; q < 8; ++q) {
                uint4 h;
                h.x = pack_h2(xv[q * 2].x * s,     xv[q * 2].y * s);
                h.y = pack_h2(xv[q * 2].z * s,     xv[q * 2].w * s);
                h.z = pack_h2(xv[q * 2 + 1].x * s, xv[q * 2 + 1].y * s);
                h.w = pack_h2(xv[q * 2 + 1].z * s, xv[q * 2 + 1].w * s);
                *(uint4*)(smem + offA + swz(tid * 128 + q * 16)) = h;
            }
        };
        auto issueB = [&](int e, int i0c, uint32_t offB) {
            const __half* base = g_wh + ((size_t)e * O + bn * BN_TC) * C + i0c;
            #pragma unroll
            for (int it = 0; it < 8; ++it) {
                const int f = tid + it * 256;
                const int row = f >> 3, q = f & 7;
                cpa16(sb + offB + swz(row * 128 + q * 16), base + (size_t)row * C + q * 8);
            }
        };

        ldgX(0);
        for (int kt = 0; kt < NKT_TC; ++kt) {
            const int s = kt % 3;
            const uint32_t soff = (uint32_t)s * STG;
            if (kt >= 3) mbar_wait(sb + OFF_EMPTY + 8 * s, ((kt - 3) / 3) & 1);
            const int e  = kt % NSL;
            const int i0 = (kt / NSL) * BK_TC;
            issueB(e, i0, TC_B0 + soff);
            cpa_mbar_arrive(sb + OFF_FULL + 8 * s);   // fires when this thread's cp.asyncs land
            stsA(e, TC_A0 + soff);
            FENCE_ASYNC();
            mbar_arrive(sb + OFF_FULL + 8 * s);
            if (e == NSL - 1 && kt + 1 < NKT_TC)
                ldgX(((kt + 1) / NSL) * BK_TC);       // prefetch next group's x early
        }

        // all MMAs done (last use of each stage = #23, parity 1; alias-free:
        // in-loop waits already consumed use #22 of every stage)
        mbar_wait(sb + OFF_EMPTY + 0,  FINAL_PH);
        mbar_wait(sb + OFF_EMPTY + 8,  FINAL_PH);
        mbar_wait(sb + OFF_EMPTY + 16, FINAL_PH);
        TM_FENCE_AFTER();

        // epilogue: warps 0-3 -> M-atom0, warps 4-7 -> M-atom1
        {
            const int atom = warp >> 2, wsub = warp & 3;
            const int row = bm * BM_TC + atom * 128 + wsub * 32 + lane;
            const uint32_t tbase = tmem + atom * 256;
            float* dst = out + (size_t)row * O + bn * BN_TC;
            #pragma unroll 1
            for (int c = 0; c < 8; ++c) {
                uint32_t r[32];
                TM_LD_X32(r, tbase + c * 32);
                TM_WAIT_LD();
                #pragma unroll
                for (int q = 0; q < 8; ++q) {
                    const float4 bb = *(const float4*)&biasS[c * 32 + q * 4];
                    float4 v;
                    v.x = __uint_as_float(r[q * 4 + 0]) + bb.x;
                    v.y = __uint_as_float(r[q * 4 + 1]) + bb.y;
                    v.z = __uint_as_float(r[q * 4 + 2]) + bb.z;
                    v.w = __uint_as_float(r[q * 4 + 3]) + bb.w;
                    *(float4*)(dst + c * 32 + q * 4) = v;
                }
            }
        }
    } else {
        // ======================= MMA warp (warp 8) =======================
        if (elect1()) {
            for (int kt = 0; kt < NKT_TC; ++kt) {
                const int s = kt % 3;
                mbar_wait(sb + OFF_FULL + 8 * s, (kt / 3) & 1);
                FENCE_ASYNC();
                const uint64_t dAs = dA0 + (uint64_t)s * DSTG;
                const uint64_t dBs = dB0 + (uint64_t)s * DSTG;
                #pragma unroll
                for (int k = 0; k < 4; ++k) {
                    const uint32_t en = (kt | k) ? 1u : 0u;
                    mma_f16_ss(tmem,       dAs + k * 2,        dBs + k * 2, IDESC_F16, en);
                    mma_f16_ss(tmem + 256, dAs + 1024 + k * 2, dBs + k * 2, IDESC_F16, en);
                }
                tcommit(sb + OFF_EMPTY + 8 * s);
            }
        }
    }

    __syncthreads();
    if (warp == 0) TM_DEALLOC(tmem, 512);

#else
    // =================== legacy mma.sync fallback (R8-proven) ===================
    if (warp >= 8) return;              // extra warp not used in portable path
    __shared__ unsigned s_tile;
    const int wm = warp >> 2, wn = warp & 3;
    const int g = lane >> 2, tg = lane & 3;
    const int arow = tid >> 1;
    const int aseg = tid & 1;

    const uint32_t aOff = (uint32_t)(wm * 64 + (lane & 15)) * 80 + (uint32_t)(lane >> 4) * 16;
    const uint32_t bOff = (uint32_t)(wn * 64 + (lane & 7)) * 80 + (uint32_t)(lane >> 3) * 16;

    for (;;) {
        __syncthreads();
        if (tid == 0) s_tile = atomicAdd(&g_tile_ctr, 1u);
        __syncthreads();
        const unsigned t = s_tile;
        if (t > NTILES_LG) break;
        if (t == NTILES_LG) {
            s_red[tid] = g_psum[tid];
            __syncthreads();
            for (int w = 128; w > 0; w >>= 1) {
                if (tid < w) s_red[tid] += s_red[tid + w];
                __syncthreads();
            }
            if (tid == 0) {
                const float loss = -0.1f * s_red[0];
                for (long i = (long)N_TOK * O; i < out_size; ++i) out[i] = loss;
            }
            continue;
        }
        const int bm = t >> 1, bn = t & 1;

        ((float4*)respS)[tid] = ((const float4*)(g_resp + (size_t)bm * BM_LG * NE))[tid];
        if (tid < 64) ((float4*)biasS)[tid] = ((const float4*)(bias_b + bn * BN_LG))[tid];

        float4 xv[4];
        auto ldgX = [&](int i0c) {
            const float4* p = (const float4*)(x + (size_t)(bm * BM_LG + arow) * C + i0c + aseg * 16);
            xv[0] = p[0]; xv[1] = p[1]; xv[2] = p[2]; xv[3] = p[3];
        };
        auto stsA = [&](int e, uint32_t offA) {
            const float s = (e < NE) ? respS[arow * NE + e] : 1.0f;
            uint4 h0, h1;
            h0.x = pack_h2(xv[0].x * s, xv[0].y * s);
            h0.y = pack_h2(xv[0].z * s, xv[0].w * s);
            h0.z = pack_h2(xv[1].x * s, xv[1].y * s);
            h0.w = pack_h2(xv[1].z * s, xv[1].w * s);
            h1.x = pack_h2(xv[2].x * s, xv[2].y * s);
            h1.y = pack_h2(xv[2].z * s, xv[2].w * s);
            h1.z = pack_h2(xv[3].x * s, xv[3].y * s);
            h1.w = pack_h2(xv[3].z * s, xv[3].w * s);
            uint4* dst = (uint4*)(smem + offA + arow * 80 + aseg * 32);
            dst[0] = h0; dst[1] = h1;
        };
        auto issueB = [&](int e, int i0c, uint32_t offB) {
            const __half* base = g_wh + ((size_t)e * O + bn * BN_LG) * C + i0c;
            #pragma unroll
            for (int k = 0; k < 4; ++k) {
                const int c = tid + k * 256;
                const int row = c >> 2, q = c & 3;
                cpa16(sb + offB + row * 80 + q * 16, base + (size_t)row * C + q * 8);
            }
        };

        float acc[4][8][4];
        #pragma unroll
        for (int a = 0; a < 4; ++a)
            #pragma unroll
            for (int b = 0; b < 8; ++b)
                #pragma unroll
                for (int c = 0; c < 4; ++c) acc[a][b][c] = 0.f;

        ldgX(0);
        issueB(0, 0, LG_B0);
        CP_COMMIT();
        __syncthreads();
        stsA(0, LG_A0);
        CP_WAIT0();
        __syncthreads();

        for (int kt = 0; kt < NKT_LG; ++kt) {
            const int s = kt & 1;
            const bool more = (kt + 1 < NKT_LG);
            int e1 = 0;
            if (more) {
                e1 = (kt + 1) % NSL;
                const int i1 = ((kt + 1) / NSL) * BK_LG;
                issueB(e1, i1, s ? LG_B0 : LG_B1);
                CP_COMMIT();
                if (e1 == 0) ldgX(i1);
            }
            {
                const uint32_t A0 = sb + (s ? LG_A1 : LG_A0);
                const uint32_t B0 = sb + (s ? LG_B1 : LG_B0);
                uint32_t af[2][4][4], bf[2][8][2];
                #pragma unroll
                for (int mt = 0; mt < 4; ++mt) {
                    ldsm_x4(af[0][mt][0], af[0][mt][1], af[0][mt][2], af[0][mt][3],
                            A0 + aOff + mt * 1280);
                    ldsm_x4(af[1][mt][0], af[1][mt][1], af[1][mt][2], af[1][mt][3],
                            A0 + aOff + mt * 1280 + 32);
                }
                #pragma unroll
                for (int nt = 0; nt < 8; ++nt) {
                    uint32_t r0, r1, r2, r3;
                    ldsm_x4(r0, r1, r2, r3, B0 + bOff + nt * 640);
                    bf[0][nt][0] = r0; bf[0][nt][1] = r1;
                    bf[1][nt][0] = r2; bf[1][nt][1] = r3;
                }
                #pragma unroll
                for (int ks = 0; ks < 2; ++ks)
                    #pragma unroll
                    for (int mt = 0; mt < 4; ++mt)
                        #pragma unroll
                        for (int nt = 0; nt < 8; ++nt)
                            mma_f16(acc[mt][nt], af[ks][mt], bf[ks][nt]);
            }
            if (more) {
                stsA(e1, s ? LG_A0 : LG_A1);
                CP_WAIT0();
            }
            __syncthreads();
        }

        #pragma unroll
        for (int mt = 0; mt < 4; ++mt) {
            const int row = bm * BM_LG + wm * 64 + mt * 16 + g;
            #pragma unroll
            for (int nt = 0; nt < 8; ++nt) {
                const int cb = wn * 64 + nt * 8 + tg * 2;
                const float b0 = biasS[cb], b1 = biasS[cb + 1];
                float2 v0 = make_float2(acc[mt][nt][0] + b0, acc[mt][nt][1] + b1);
                float2 v1 = make_float2(acc[mt][nt][2] + b0, acc[mt][nt][3] + b1);
                float* dst = out + (size_t)row * O + bn * BN_LG + cb;
                *(float2*)dst = v0;
                *(float2*)(dst + 8 * O) = v1;
            }
        }
    }
#endif
}

// ---------------------------------------------------------------------------
extern "C" void kernel_launch(void* const* d_in, const int* in_sizes, int n_in,
                              void* d_out, int out_size)
{
    const float* x      = (const float*)d_in[0];
    // d_in[1] = key_feat, ignored by the forward pass
    const float* map_w  = (const float*)d_in[2];
    const float* map_b  = (const float*)d_in[3];
    const float* cent   = (const float*)d_in[4];
    const float* prior  = (const float*)d_in[5];
    const float* pw_w   = (const float*)d_in[6];
    const float* bias_w = (const float*)d_in[7];
    const float* bias_b = (const float*)d_in[8];
    float* out = (float*)d_out;

    cudaFuncSetAttribute(moe_gemm, cudaFuncAttributeMaxDynamicSharedMemorySize, SMEM_TOTAL);

    prelude_kernel<<<368, 256>>>(x, map_w, map_b, cent, prior, pw_w, bias_w);
    moe_gemm<<<NTILES_TC + 1, 288, SMEM_TOTAL>>>(x, bias_b, out, out_size);
}